// round 17
// baseline (speedup 1.0000x reference)
#include <cuda_runtime.h>
#include <cstdint>
#include <cstddef>

static constexpr int   B      = 8;
static constexpr int   N      = 32768;
static constexpr int   K      = 128;
static constexpr int   D      = 64;
static constexpr int   ITERS  = 10;
static constexpr float EPS    = 1e-8f;
static constexpr float LOG2E  = 1.4426950408889634f;

static constexpr int BPB   = 256;         // blocks per batch -> grid 2048, 1 tile per block
static constexpr int NB    = B * BPB;     // 2048 blocks
static constexpr int TILE  = 128;         // points per block (== chunk)
static constexpr int BT    = 128;         // k_iter block threads (4 warps)

static constexpr int GEMM_CH = 64;        // n-chunks per batch for node_feats GEMM -> 512 blocks
static constexpr int TN      = 32;        // points per GEMM smem tile
static constexpr int FPAD    = 4;         // s_f row padding (keeps float4 alignment)

typedef unsigned long long u64;

// ---------------- device scratch (no allocations allowed) ----------------
__device__ float g_buf[ITERS][B][K][4];   // per-iter accumulators: denom, Mx, My, Mz
__device__ float g_cinit[B][K][3];
__device__ float g_ssum[B];
__device__ float g_nfacc[B * K * D];

// ---------------- small asm helpers ----------------
__device__ __forceinline__ float ex2f(float x) {
    float r; asm("ex2.approx.ftz.f32 %0, %1;" : "=f"(r) : "f"(x)); return r;
}
__device__ __forceinline__ u64 pack2(float lo, float hi) {
    u64 r; asm("mov.b64 %0, {%1, %2};" : "=l"(r) : "f"(lo), "f"(hi)); return r;
}
__device__ __forceinline__ void unpack2(u64 v, float& lo, float& hi) {
    asm("mov.b64 {%0, %1}, %2;" : "=f"(lo), "=f"(hi) : "l"(v));
}
__device__ __forceinline__ void ffma2(u64& d, u64 a, u64 b) {
    asm("fma.rn.f32x2 %0, %1, %2, %0;" : "+l"(d) : "l"(a), "l"(b));
}

// ---------------- kernel 1: init (zero scratch + centers + score sums, fused) ----------------
__global__ void k_init(const float* __restrict__ xyz, const float* __restrict__ osc) {
    const int tid = threadIdx.x;
    const int gidx = blockIdx.x * 256 + tid;       // grid 256 -> 65536 threads

    // zero stripes of scratch
    float* gb = &g_buf[0][0][0][0];
    if (gidx < ITERS * B * K * 4) gb[gidx] = 0.f;
    if (gidx < B * K * D)         g_nfacc[gidx] = 0.f;

    // blocks 0..B-1 additionally do per-batch init
    if (blockIdx.x < B) {
        const int b = blockIdx.x;
        __shared__ float red[256];
        const float* w = osc + (size_t)b * N;
        float s = 0.f;
        for (int n = tid; n < N; n += 256) s += w[n];
        red[tid] = s;
        __syncthreads();
        for (int st = 128; st > 0; st >>= 1) {
            if (tid < st) red[tid] += red[tid + st];
            __syncthreads();
        }
        if (tid == 0) g_ssum[b] = red[0] + EPS;
        if (tid < K) {
            int n0 = tid * (N / K);
            const float* xb = xyz + (size_t)b * 3 * N;
            g_cinit[b][tid][0] = xb[n0];
            g_cinit[b][tid][1] = xb[N + n0];
            g_cinit[b][tid][2] = xb[2 * N + n0];
        }
    }
}

// ---------------- kernel 2: one clustering iteration (launched ITERS times) ----------------
// 128-thread blocks (4 warps), one 128-point tile per block -> up to 16 blocks/SM.
// Single-pass shuffle softmax, cluster-per-lane, block-level smem moment reduction.
template <bool FIN>
__global__ void __launch_bounds__(BT, 8)
k_iter(const float* __restrict__ xyz, const float* __restrict__ osc,
       float* __restrict__ out_gamma, int it) {
    const int b    = blockIdx.x >> 8;         // / BPB (=256)
    const int slot = blockIdx.x & (BPB - 1);
    const int tb   = slot * TILE;
    const int tid  = threadIdx.x;
    const int lane = tid & 31;
    const int wid  = tid >> 5;                // 0..3

    __shared__ float4 s_A[K];          // center constants (2*log2e*c, -log2e*|c|^2)
    __shared__ float4 s_pt[TILE];      // staged points: x0,x1,x2,w
    __shared__ float  s_mom[32 * 17];  // block moment reduction, stride-17 (conflict-free)

    const float* x0p = xyz + (size_t)b * 3 * N;

    // -- stage tile + zero moment scratch + derive A_k (one sync for all) --
    const int gi = tb + tid;
    float4 pd;
    pd.x = x0p[gi]; pd.y = x0p[N + gi]; pd.z = x0p[2 * N + gi];
    pd.w = osc[(size_t)b * N + gi];
    s_pt[tid] = pd;
    s_mom[tid]       = 0.f;
    s_mom[tid + 128] = 0.f;
    s_mom[tid + 256] = 0.f;
    s_mom[tid + 384] = 0.f;
    if (tid < 32) s_mom[tid + 512] = 0.f;
    {   // tid == cluster index (BT == K)
        float c0, c1, c2;
        if (it == 0) {
            c0 = g_cinit[b][tid][0];
            c1 = g_cinit[b][tid][1];
            c2 = g_cinit[b][tid][2];
        } else {
            const float* pb = &g_buf[it - 1][b][tid][0];
            float inv = 1.0f / (pb[0] + EPS);
            c0 = pb[1] * inv; c1 = pb[2] * inv; c2 = pb[3] * inv;
        }
        s_A[tid] = make_float4(2.f * LOG2E * c0, 2.f * LOG2E * c1, 2.f * LOG2E * c2,
                               -LOG2E * (c0 * c0 + c1 * c1 + c2 * c2));
    }
    __syncthreads();

    // each lane owns 4 consecutive clusters
    const float4 A0 = s_A[lane * 4 + 0];
    const float4 A1 = s_A[lane * 4 + 1];
    const float4 A2 = s_A[lane * 4 + 2];
    const float4 A3 = s_A[lane * 4 + 3];

    float aD0 = 0.f, aD1 = 0.f, aD2 = 0.f, aD3 = 0.f;
    float aX0 = 0.f, aX1 = 0.f, aX2 = 0.f, aX3 = 0.f;
    float aY0 = 0.f, aY1 = 0.f, aY2 = 0.f, aY3 = 0.f;
    float aZ0 = 0.f, aZ1 = 0.f, aZ2 = 0.f, aZ3 = 0.f;

    #pragma unroll 8
    for (int m = 0; m < 32; ++m) {
        const int p = wid + m * 4;            // 4 warps stride the 128-point tile
        const float4 P = s_pt[p];

        float t0 = fmaf(A0.x, P.x, A0.w); t0 = fmaf(A0.y, P.y, t0); t0 = fmaf(A0.z, P.z, t0);
        float t1 = fmaf(A1.x, P.x, A1.w); t1 = fmaf(A1.y, P.y, t1); t1 = fmaf(A1.z, P.z, t1);
        float t2 = fmaf(A2.x, P.x, A2.w); t2 = fmaf(A2.y, P.y, t2); t2 = fmaf(A2.z, P.z, t2);
        float t3 = fmaf(A3.x, P.x, A3.w); t3 = fmaf(A3.y, P.y, t3); t3 = fmaf(A3.z, P.z, t3);

        const float e0 = ex2f(t0), e1 = ex2f(t1), e2 = ex2f(t2), e3 = ex2f(t3);
        float s = (e0 + e1) + (e2 + e3);
        #pragma unroll
        for (int o = 16; o > 0; o >>= 1) s += __shfl_xor_sync(0xffffffffu, s, o);

        const float u = __fdividef(P.w, s);
        const float g0 = e0 * u, g1 = e1 * u, g2 = e2 * u, g3 = e3 * u;

        aD0 += g0; aX0 = fmaf(g0, P.x, aX0); aY0 = fmaf(g0, P.y, aY0); aZ0 = fmaf(g0, P.z, aZ0);
        aD1 += g1; aX1 = fmaf(g1, P.x, aX1); aY1 = fmaf(g1, P.y, aY1); aZ1 = fmaf(g1, P.z, aZ1);
        aD2 += g2; aX2 = fmaf(g2, P.x, aX2); aY2 = fmaf(g2, P.y, aY2); aZ2 = fmaf(g2, P.z, aZ2);
        aD3 += g3; aX3 = fmaf(g3, P.x, aX3); aY3 = fmaf(g3, P.y, aY3); aZ3 = fmaf(g3, P.z, aZ3);

        if (FIN) {
            *(float4*)&out_gamma[((size_t)(b * N + tb + p)) * K + lane * 4]
                = make_float4(g0, g1, g2, g3);
        }
    }

    // -- block-level smem reduction of moments (stride-17 layout: lane*17 + idx) --
    {
        float* sm = &s_mom[lane * 17];
        atomicAdd(sm + 0,  aD0); atomicAdd(sm + 1,  aX0); atomicAdd(sm + 2,  aY0); atomicAdd(sm + 3,  aZ0);
        atomicAdd(sm + 4,  aD1); atomicAdd(sm + 5,  aX1); atomicAdd(sm + 6,  aY1); atomicAdd(sm + 7,  aZ1);
        atomicAdd(sm + 8,  aD2); atomicAdd(sm + 9,  aX2); atomicAdd(sm + 10, aY2); atomicAdd(sm + 11, aZ2);
        atomicAdd(sm + 12, aD3); atomicAdd(sm + 13, aX3); atomicAdd(sm + 14, aY3); atomicAdd(sm + 15, aZ3);
    }
    __syncthreads();

    // -- flush: one global atomic per (k,comp) per block; 4 per thread --
    {
        float* pb = &g_buf[it][b][0][0];
        #pragma unroll
        for (int r = 0; r < 4; ++r) {
            int t = tid + r * BT;                  // 0..511 = lane_src*16 + idx
            float val = s_mom[(t >> 4) * 17 + (t & 15)];
            atomicAdd(pb + t, val);                // global offset = (t>>4)*16 + (t&15) = t
        }
    }
}

// ---------------- kernel 3: node_feats = gamma^T @ feats (split-N, f32x2 FMA) ----------------
__global__ void __launch_bounds__(128)
k_nf(const float* __restrict__ feats, const float* __restrict__ gamma) {
    const int b  = blockIdx.y;
    const int n0 = blockIdx.x * (N / GEMM_CH);
    const int tid = threadIdx.x;
    const int k0 = (tid >> 3) * 8;   // 16 k-groups of 8
    const int d0 = (tid & 7) * 8;    // 8 d-groups of 8

    __shared__ float s_g[TN][K];          // 16 KB
    __shared__ float s_f[TN][D + FPAD];   // padded by 4 -> float4-aligned rows

    u64 acc[8][4];
    #pragma unroll
    for (int i = 0; i < 8; i++)
        #pragma unroll
        for (int c = 0; c < 4; c++) acc[i][c] = pack2(0.f, 0.f);

    const float* gbase = gamma + (size_t)b * N * K;
    const float* fbase = feats + (size_t)b * D * N;

    for (int t0 = n0; t0 < n0 + N / GEMM_CH; t0 += TN) {
        __syncthreads();
        {   // gamma tile: TN*K floats = 1024 float4, 8 per thread, coalesced
            const float4* src = (const float4*)(gbase + (size_t)t0 * K);
            float4* dst = (float4*)&s_g[0][0];
            #pragma unroll
            for (int j = 0; j < 8; j++) dst[tid + j * 128] = src[tid + j * 128];
        }
        {   // feats tile: D rows of TN consecutive n, transposed into s_f[n][d]
            #pragma unroll
            for (int j = 0; j < 16; j++) {
                int li = tid + j * 128;          // 0..2047
                int d = li >> 5, i = li & 31;
                s_f[i][d] = fbase[(size_t)d * N + t0 + i];
            }
        }
        __syncthreads();

        for (int i = 0; i < TN; i++) {
            float4 ga  = *(const float4*)&s_g[i][k0];
            float4 gb2 = *(const float4*)&s_g[i][k0 + 4];
            float4 fa  = *(const float4*)&s_f[i][d0];
            float4 fb  = *(const float4*)&s_f[i][d0 + 4];
            u64 f01 = pack2(fa.x, fa.y), f23 = pack2(fa.z, fa.w);
            u64 f45 = pack2(fb.x, fb.y), f67 = pack2(fb.z, fb.w);
            float gk[8] = {ga.x, ga.y, ga.z, ga.w, gb2.x, gb2.y, gb2.z, gb2.w};
            #pragma unroll
            for (int kk = 0; kk < 8; kk++) {
                u64 gg = pack2(gk[kk], gk[kk]);
                ffma2(acc[kk][0], gg, f01);
                ffma2(acc[kk][1], gg, f23);
                ffma2(acc[kk][2], gg, f45);
                ffma2(acc[kk][3], gg, f67);
            }
        }
    }

    #pragma unroll
    for (int kk = 0; kk < 8; kk++)
        #pragma unroll
        for (int c = 0; c < 4; c++) {
            float lo, hi; unpack2(acc[kk][c], lo, hi);
            float* dst = &g_nfacc[((size_t)b * K + (k0 + kk)) * D + d0 + c * 2];
            atomicAdd(dst, lo);
            atomicAdd(dst + 1, hi);
        }
}

// ---------------- kernel 4: finalize node_feats + pi + node_xyz (fused) ----------------
__global__ void k_nf_fin(float* __restrict__ out_nf, float* __restrict__ out_pi,
                         float* __restrict__ out_nxyz) {
    int i = blockIdx.x * blockDim.x + threadIdx.x;   // 65536 threads
    if (i < B * K * D) {
        int b = i / (K * D);
        int k = (i % (K * D)) / D;
        float dn = g_buf[ITERS - 1][b][k][0] + EPS;
        out_nf[i] = g_nfacc[i] / dn;
    }
    if (i < B * K) {
        int b = i / K, k = i % K;
        const float* pb = &g_buf[ITERS - 1][b][k][0];
        float raw = pb[0];
        float inv = 1.0f / (raw + EPS);
        out_pi[i] = raw / g_ssum[b];
        out_nxyz[i * 3 + 0] = pb[1] * inv;
        out_nxyz[i * 3 + 1] = pb[2] * inv;
        out_nxyz[i * 3 + 2] = pb[3] * inv;
    }
}

// ---------------- launch ----------------
extern "C" void kernel_launch(void* const* d_in, const int* in_sizes, int n_in,
                              void* d_out, int out_size) {
    const float* xyz   = (const float*)d_in[0];
    const float* feats = (const float*)d_in[1];
    const float* osc   = (const float*)d_in[2];

    float* out   = (float*)d_out;
    float* ogam  = out;
    float* opi   = ogam + (size_t)B * N * K;
    float* oxyz  = opi + B * K;
    float* onf   = oxyz + B * K * 3;

    k_init<<<256, 256>>>(xyz, osc);
    for (int it = 0; it < ITERS - 1; ++it)
        k_iter<false><<<NB, BT>>>(xyz, osc, ogam, it);
    k_iter<true><<<NB, BT>>>(xyz, osc, ogam, ITERS - 1);
    dim3 gg(GEMM_CH, B);
    k_nf<<<gg, 128>>>(feats, ogam);
    k_nf_fin<<<256, 256>>>(onf, opi, oxyz);
}